// round 1
// baseline (speedup 1.0000x reference)
#include <cuda_runtime.h>
#include <stdint.h>

#define IMG_H 2048
#define IMG_W 2048
#define NPIX (IMG_H * IMG_W)
#define NT 8
#define TILE 256
#define NBINS 256

// scratch (device globals: allocation-free, per the harness rules)
__device__ unsigned int g_hist[NT * NT * NBINS];
__device__ float g_lut[NT * NT * NBINS];

__device__ __forceinline__ float f_lab(float v) {
    return (v > 0.008856f) ? cbrtf(v) : (7.787f * v + 16.0f / 116.0f);
}

__device__ __forceinline__ float clamp01(float v) {
    return fminf(fmaxf(v, 0.0f), 1.0f);
}

// ---------------------------------------------------------------------------
// Kernel 0: zero the global histogram (graph replays need deterministic state)
// ---------------------------------------------------------------------------
__global__ void k_zero() {
    int i = blockIdx.x * blockDim.x + threadIdx.x;
    g_hist[i] = 0u;
}

// ---------------------------------------------------------------------------
// Kernel 1: per-tile histograms of L8.
// Block = 512 threads, covers 16 full image rows (one tile-row band slice).
// Shared hist: 8 x-tiles * 256 bins.
// ---------------------------------------------------------------------------
__global__ __launch_bounds__(512) void k_hist(const float* __restrict__ rp,
                                              const float* __restrict__ gp,
                                              const float* __restrict__ bp) {
    __shared__ unsigned int sh[NT * NBINS];
    const int tid = threadIdx.x;                   // 0..511
    for (int i = tid; i < NT * NBINS; i += 512) sh[i] = 0u;
    __syncthreads();

    const int row0 = blockIdx.x * 16;
    const int xt = (tid * 4) >> 8;                 // x-tile of this thread's 4 px (4-aligned)

    for (int r = 0; r < 16; ++r) {
        const int base = (row0 + r) * IMG_W + tid * 4;
        const float4 R = *(const float4*)(rp + base);
        const float4 G = *(const float4*)(gp + base);
        const float4 B = *(const float4*)(bp + base);
#pragma unroll
        for (int k = 0; k < 4; ++k) {
            const float rr = (&R.x)[k], gg = (&G.x)[k], bb = (&B.x)[k];
            const float Y = 0.212671f * rr + 0.715160f * gg + 0.072169f * bb;
            const float L = 116.0f * f_lab(Y) - 16.0f;
            int l8 = (int)rintf(L * 2.55f);
            l8 = min(max(l8, 0), 255);
            atomicAdd(&sh[xt * NBINS + l8], 1u);
        }
    }
    __syncthreads();

    const int ty = row0 >> 8;                      // tile row
    for (int i = tid; i < NT * NBINS; i += 512) {
        const unsigned v = sh[i];
        if (v) atomicAdd(&g_hist[(ty * NT + (i >> 8)) * NBINS + (i & 255)], v);
    }
}

// ---------------------------------------------------------------------------
// Kernel 2: clip + redistribute + cdf -> LUT. One block per tile.
// All arithmetic is exact in fp32 (integer-valued * 2^-8 terms, cdf <= 2^16),
// so LUT matches the reference bit-for-bit given identical histograms.
// ---------------------------------------------------------------------------
__global__ __launch_bounds__(NBINS) void k_lut() {
    __shared__ float sv[NBINS];
    __shared__ unsigned int s_ex;
    const int t = threadIdx.x, b = blockIdx.x;
    if (t == 0) s_ex = 0u;
    __syncthreads();

    const unsigned h = g_hist[b * NBINS + t];
    const unsigned over = (h > 2560u) ? (h - 2560u) : 0u;  // clip = 10*65536/256
    if (over) atomicAdd(&s_ex, over);
    __syncthreads();

    sv[t] = (float)min(h, 2560u) + (float)s_ex * (1.0f / 256.0f);
    __syncthreads();
    if (t == 0) {                                   // sequential cumsum (exact anyway)
        float run = 0.0f;
#pragma unroll 8
        for (int i = 0; i < NBINS; ++i) { run += sv[i]; sv[i] = run; }
    }
    __syncthreads();

    float lut = rintf(sv[t] * (255.0f / 65536.0f));
    lut = fminf(fmaxf(lut, 0.0f), 255.0f);
    g_lut[b * NBINS + t] = lut;
}

// ---------------------------------------------------------------------------
// Kernel 3: per-pixel apply. Block = 256 threads over a 16-row x 256-col
// region. Interpolation boundaries are at y,x = 384+256k, so a 16-aligned
// row stripe shares its (yt0,yt1) pair, and a 256-aligned column block draws
// its x-tiles from {bx-1, bx, bx+1}. 6 LUTs (6 KB) live in shared memory.
// ---------------------------------------------------------------------------
__global__ __launch_bounds__(256) void k_apply(const float* __restrict__ in,
                                               float* __restrict__ out) {
    __shared__ float slut[6][NBINS];
    const int tid = threadIdx.x;     // 0..255
    const int bx = blockIdx.x;       // 0..7
    const int by = blockIdx.y;       // 0..127
    const int row0 = by * 16;

    const float fy0 = fminf(fmaxf((row0 + 0.5f) * (1.0f / 256.0f) - 0.5f, 0.0f), 7.0f);
    const int yt0 = (int)floorf(fy0);
    const int yt1 = min(yt0 + 1, NT - 1);

#pragma unroll
    for (int s = 0; s < 3; ++s) {
        const int xt = min(max(bx - 1 + s, 0), NT - 1);
        slut[s][tid]     = g_lut[(yt0 * NT + xt) * NBINS + tid];
        slut[3 + s][tid] = g_lut[(yt1 * NT + xt) * NBINS + tid];
    }
    __syncthreads();

    const int x = bx * 256 + tid;
    const float fx = fminf(fmaxf((x + 0.5f) * (1.0f / 256.0f) - 0.5f, 0.0f), 7.0f);
    const int x0c = (int)floorf(fx);
    const float wx = fx - (float)x0c;
    const int xs0 = x0c - bx + 1;                  // in [0,2]
    const int xs1 = min(x0c + 1, NT - 1) - bx + 1; // in [0,2]

    const float* __restrict__ rp = in;
    const float* __restrict__ gp = in + NPIX;
    const float* __restrict__ bp = in + 2 * NPIX;

    for (int r = 0; r < 16; ++r) {
        const int row = row0 + r;
        const int idx = row * IMG_W + x;
        const float rr = rp[idx], gg = gp[idx], bb = bp[idx];

        // rgb2lab
        const float Xv = (0.412453f * rr + 0.357580f * gg + 0.180423f * bb) *
                         (1.0f / 0.950456f);
        const float Yv = 0.212671f * rr + 0.715160f * gg + 0.072169f * bb;
        const float Zv = (0.019334f * rr + 0.119193f * gg + 0.950227f * bb) *
                         (1.0f / 1.088754f);
        const float fX = f_lab(Xv), fY = f_lab(Yv), fZ = f_lab(Zv);
        const float L = 116.0f * fY - 16.0f;
        const float av = 500.0f * (fX - fY);
        const float bv = 200.0f * (fY - fZ);

        int l8 = (int)rintf(L * 2.55f);
        l8 = min(max(l8, 0), 255);

        const float fyr = fminf(fmaxf((row + 0.5f) * (1.0f / 256.0f) - 0.5f, 0.0f), 7.0f);
        const float wy = fyr - (float)yt0;

        const float top = (1.0f - wx) * slut[xs0][l8] + wx * slut[xs1][l8];
        const float bot = (1.0f - wx) * slut[3 + xs0][l8] + wx * slut[3 + xs1][l8];
        const float Leq = ((1.0f - wy) * top + wy * bot) * (100.0f / 255.0f);

        // lab2rgb
        const float fy2 = (Leq + 16.0f) * (1.0f / 116.0f);
        const float fx2 = fy2 + av * (1.0f / 500.0f);
        const float fz2 = fy2 - bv * (1.0f / 200.0f);
        const float x3 = fx2 * fx2 * fx2;
        const float y3 = fy2 * fy2 * fy2;
        const float z3 = fz2 * fz2 * fz2;
        const float Xo = ((x3 > 0.008856f) ? x3
                                           : (fx2 - 16.0f / 116.0f) * (1.0f / 7.787f)) *
                         0.950456f;
        const float Yo = ((y3 > 0.008856f) ? y3
                                           : (fy2 - 16.0f / 116.0f) * (1.0f / 7.787f));
        const float Zo = ((z3 > 0.008856f) ? z3
                                           : (fz2 - 16.0f / 116.0f) * (1.0f / 7.787f)) *
                         1.088754f;

        const float ro =  3.240479f * Xo - 1.537150f * Yo - 0.498535f * Zo;
        const float go = -0.969256f * Xo + 1.875992f * Yo + 0.041556f * Zo;
        const float bo =  0.055648f * Xo - 0.204043f * Yo + 1.057311f * Zo;

        out[idx]            = clamp01(ro);
        out[NPIX + idx]     = clamp01(go);
        out[2 * NPIX + idx] = clamp01(bo);
    }
}

// ---------------------------------------------------------------------------
extern "C" void kernel_launch(void* const* d_in, const int* in_sizes, int n_in,
                              void* d_out, int out_size) {
    const float* in = (const float*)d_in[0];
    float* out = (float*)d_out;
    (void)in_sizes; (void)n_in; (void)out_size;

    k_zero<<<NT * NT, NBINS>>>();
    k_hist<<<IMG_H / 16, 512>>>(in, in + NPIX, in + 2 * NPIX);
    k_lut<<<NT * NT, NBINS>>>();
    k_apply<<<dim3(NT, IMG_H / 16), 256>>>(in, out);
}

// round 2
// speedup vs baseline: 1.0012x; 1.0012x over previous
#include <cuda_runtime.h>
#include <stdint.h>

#define IMG_H 2048
#define IMG_W 2048
#define NPIX (IMG_H * IMG_W)
#define NT 8
#define TILE 256
#define NBINS 256

// scratch (device globals: allocation-free, per the harness rules)
__device__ unsigned int g_hist[NT * NT * NBINS];
__device__ float g_lut[NT * NT * NBINS];

__device__ __forceinline__ float f_lab(float v) {
    return (v > 0.008856f) ? cbrtf(v) : (7.787f * v + 16.0f / 116.0f);
}

__device__ __forceinline__ float clamp01(float v) {
    return fminf(fmaxf(v, 0.0f), 1.0f);
}

// ---------------------------------------------------------------------------
// Kernel 0: zero the global histogram (graph replays need deterministic state)
// ---------------------------------------------------------------------------
__global__ void k_zero() {
    int i = blockIdx.x * blockDim.x + threadIdx.x;
    g_hist[i] = 0u;
}

// ---------------------------------------------------------------------------
// Kernel 1: per-tile histograms of L8.
// Block = 512 threads, covers 16 full image rows (one tile-row band slice).
// Shared hist: 8 x-tiles * 256 bins.
// ---------------------------------------------------------------------------
__global__ __launch_bounds__(512) void k_hist(const float* __restrict__ rp,
                                              const float* __restrict__ gp,
                                              const float* __restrict__ bp) {
    __shared__ unsigned int sh[NT * NBINS];
    const int tid = threadIdx.x;                   // 0..511
    for (int i = tid; i < NT * NBINS; i += 512) sh[i] = 0u;
    __syncthreads();

    const int row0 = blockIdx.x * 16;
    const int xt = (tid * 4) >> 8;                 // x-tile of this thread's 4 px (4-aligned)

    for (int r = 0; r < 16; ++r) {
        const int base = (row0 + r) * IMG_W + tid * 4;
        const float4 R = *(const float4*)(rp + base);
        const float4 G = *(const float4*)(gp + base);
        const float4 B = *(const float4*)(bp + base);
#pragma unroll
        for (int k = 0; k < 4; ++k) {
            const float rr = (&R.x)[k], gg = (&G.x)[k], bb = (&B.x)[k];
            const float Y = 0.212671f * rr + 0.715160f * gg + 0.072169f * bb;
            const float L = 116.0f * f_lab(Y) - 16.0f;
            int l8 = (int)rintf(L * 2.55f);
            l8 = min(max(l8, 0), 255);
            atomicAdd(&sh[xt * NBINS + l8], 1u);
        }
    }
    __syncthreads();

    const int ty = row0 >> 8;                      // tile row
    for (int i = tid; i < NT * NBINS; i += 512) {
        const unsigned v = sh[i];
        if (v) atomicAdd(&g_hist[(ty * NT + (i >> 8)) * NBINS + (i & 255)], v);
    }
}

// ---------------------------------------------------------------------------
// Kernel 2: clip + redistribute + cdf -> LUT. One block per tile.
// All arithmetic is exact in fp32 (integer-valued * 2^-8 terms, cdf <= 2^16),
// so LUT matches the reference bit-for-bit given identical histograms.
// ---------------------------------------------------------------------------
__global__ __launch_bounds__(NBINS) void k_lut() {
    __shared__ float sv[NBINS];
    __shared__ unsigned int s_ex;
    const int t = threadIdx.x, b = blockIdx.x;
    if (t == 0) s_ex = 0u;
    __syncthreads();

    const unsigned h = g_hist[b * NBINS + t];
    const unsigned over = (h > 2560u) ? (h - 2560u) : 0u;  // clip = 10*65536/256
    if (over) atomicAdd(&s_ex, over);
    __syncthreads();

    sv[t] = (float)min(h, 2560u) + (float)s_ex * (1.0f / 256.0f);
    __syncthreads();
    if (t == 0) {                                   // sequential cumsum (exact anyway)
        float run = 0.0f;
#pragma unroll 8
        for (int i = 0; i < NBINS; ++i) { run += sv[i]; sv[i] = run; }
    }
    __syncthreads();

    float lut = rintf(sv[t] * (255.0f / 65536.0f));
    lut = fminf(fmaxf(lut, 0.0f), 255.0f);
    g_lut[b * NBINS + t] = lut;
}

// ---------------------------------------------------------------------------
// Kernel 3: per-pixel apply. Block = 256 threads over a 16-row x 256-col
// region. Interpolation boundaries are at y,x = 384+256k, so a 16-aligned
// row stripe shares its (yt0,yt1) pair, and a 256-aligned column block draws
// its x-tiles from {bx-1, bx, bx+1}. 6 LUTs (6 KB) live in shared memory.
// ---------------------------------------------------------------------------
__global__ __launch_bounds__(256) void k_apply(const float* __restrict__ in,
                                               float* __restrict__ out) {
    __shared__ float slut[6][NBINS];
    const int tid = threadIdx.x;     // 0..255
    const int bx = blockIdx.x;       // 0..7
    const int by = blockIdx.y;       // 0..127
    const int row0 = by * 16;

    const float fy0 = fminf(fmaxf((row0 + 0.5f) * (1.0f / 256.0f) - 0.5f, 0.0f), 7.0f);
    const int yt0 = (int)floorf(fy0);
    const int yt1 = min(yt0 + 1, NT - 1);

#pragma unroll
    for (int s = 0; s < 3; ++s) {
        const int xt = min(max(bx - 1 + s, 0), NT - 1);
        slut[s][tid]     = g_lut[(yt0 * NT + xt) * NBINS + tid];
        slut[3 + s][tid] = g_lut[(yt1 * NT + xt) * NBINS + tid];
    }
    __syncthreads();

    const int x = bx * 256 + tid;
    const float fx = fminf(fmaxf((x + 0.5f) * (1.0f / 256.0f) - 0.5f, 0.0f), 7.0f);
    const int x0c = (int)floorf(fx);
    const float wx = fx - (float)x0c;
    const int xs0 = x0c - bx + 1;                  // in [0,2]
    const int xs1 = min(x0c + 1, NT - 1) - bx + 1; // in [0,2]

    const float* __restrict__ rp = in;
    const float* __restrict__ gp = in + NPIX;
    const float* __restrict__ bp = in + 2 * NPIX;

    for (int r = 0; r < 16; ++r) {
        const int row = row0 + r;
        const int idx = row * IMG_W + x;
        const float rr = rp[idx], gg = gp[idx], bb = bp[idx];

        // rgb2lab
        const float Xv = (0.412453f * rr + 0.357580f * gg + 0.180423f * bb) *
                         (1.0f / 0.950456f);
        const float Yv = 0.212671f * rr + 0.715160f * gg + 0.072169f * bb;
        const float Zv = (0.019334f * rr + 0.119193f * gg + 0.950227f * bb) *
                         (1.0f / 1.088754f);
        const float fX = f_lab(Xv), fY = f_lab(Yv), fZ = f_lab(Zv);
        const float L = 116.0f * fY - 16.0f;
        const float av = 500.0f * (fX - fY);
        const float bv = 200.0f * (fY - fZ);

        int l8 = (int)rintf(L * 2.55f);
        l8 = min(max(l8, 0), 255);

        const float fyr = fminf(fmaxf((row + 0.5f) * (1.0f / 256.0f) - 0.5f, 0.0f), 7.0f);
        const float wy = fyr - (float)yt0;

        const float top = (1.0f - wx) * slut[xs0][l8] + wx * slut[xs1][l8];
        const float bot = (1.0f - wx) * slut[3 + xs0][l8] + wx * slut[3 + xs1][l8];
        const float Leq = ((1.0f - wy) * top + wy * bot) * (100.0f / 255.0f);

        // lab2rgb
        const float fy2 = (Leq + 16.0f) * (1.0f / 116.0f);
        const float fx2 = fy2 + av * (1.0f / 500.0f);
        const float fz2 = fy2 - bv * (1.0f / 200.0f);
        const float x3 = fx2 * fx2 * fx2;
        const float y3 = fy2 * fy2 * fy2;
        const float z3 = fz2 * fz2 * fz2;
        const float Xo = ((x3 > 0.008856f) ? x3
                                           : (fx2 - 16.0f / 116.0f) * (1.0f / 7.787f)) *
                         0.950456f;
        const float Yo = ((y3 > 0.008856f) ? y3
                                           : (fy2 - 16.0f / 116.0f) * (1.0f / 7.787f));
        const float Zo = ((z3 > 0.008856f) ? z3
                                           : (fz2 - 16.0f / 116.0f) * (1.0f / 7.787f)) *
                         1.088754f;

        const float ro =  3.240479f * Xo - 1.537150f * Yo - 0.498535f * Zo;
        const float go = -0.969256f * Xo + 1.875992f * Yo + 0.041556f * Zo;
        const float bo =  0.055648f * Xo - 0.204043f * Yo + 1.057311f * Zo;

        out[idx]            = clamp01(ro);
        out[NPIX + idx]     = clamp01(go);
        out[2 * NPIX + idx] = clamp01(bo);
    }
}

// ---------------------------------------------------------------------------
extern "C" void kernel_launch(void* const* d_in, const int* in_sizes, int n_in,
                              void* d_out, int out_size) {
    const float* in = (const float*)d_in[0];
    float* out = (float*)d_out;
    (void)in_sizes; (void)n_in; (void)out_size;

    k_zero<<<NT * NT, NBINS>>>();
    k_hist<<<IMG_H / 16, 512>>>(in, in + NPIX, in + 2 * NPIX);
    k_lut<<<NT * NT, NBINS>>>();
    k_apply<<<dim3(NT, IMG_H / 16), 256>>>(in, out);
}

// round 4
// speedup vs baseline: 1.5091x; 1.5072x over previous
#include <cuda_runtime.h>
#include <stdint.h>

#define IMG_H 2048
#define IMG_W 2048
#define NPIX (IMG_H * IMG_W)
#define NT 8
#define NBINS 256

__device__ unsigned int g_hist[NT * NT * NBINS];
__device__ float g_lut[NT * NT * NBINS];

// fast cbrt for v in (0, ~1.1]: ex2(lg2(v)/3) via MUFU. ~1e-6 rel, 3 instrs.
__device__ __forceinline__ float cbrt_fast(float v) {
    float l, r;
    asm("lg2.approx.f32 %0, %1;" : "=f"(l) : "f"(v));
    l *= (1.0f / 3.0f);
    asm("ex2.approx.f32 %0, %1;" : "=f"(r) : "f"(l));
    return r;
}

__device__ __forceinline__ float f_lab(float v) {
    return (v > 0.008856f) ? cbrt_fast(v) : (7.787f * v + 16.0f / 116.0f);
}

__device__ __forceinline__ float clamp01(float v) {
    return fminf(fmaxf(v, 0.0f), 1.0f);
}

// ---------------------------------------------------------------------------
// Kernel 0: zero global hist (graph replays need deterministic state)
// ---------------------------------------------------------------------------
__global__ void k_zero() {
    g_hist[blockIdx.x * blockDim.x + threadIdx.x] = 0u;
}

// ---------------------------------------------------------------------------
// Kernel 1: per-tile histograms. Block = 256 thr covers 16 rows x 512 cols
// (2 x-tiles). Grid = (4, 128) = 512 blocks. Shared hist: 2 tiles x 2
// replicas x 256 bins (replica = warp&1) to halve shared-atomic conflicts.
// ---------------------------------------------------------------------------
__global__ __launch_bounds__(256) void k_hist(const float* __restrict__ rp,
                                              const float* __restrict__ gp,
                                              const float* __restrict__ bp) {
    __shared__ unsigned int sh[2][2][NBINS];     // [tile][replica][bin]
    const int tid = threadIdx.x;
    for (int i = tid; i < 2 * 2 * NBINS; i += 256) ((unsigned*)sh)[i] = 0u;
    __syncthreads();

    const int col0 = blockIdx.x * 512 + (tid & 127) * 4;
    const int row0 = blockIdx.y * 16 + (tid >> 7);
    const int tl = (tid & 127) >> 6;             // local x-tile 0/1
    const int rep = (tid >> 5) & 1;
    unsigned int* __restrict__ h = sh[tl][rep];

#pragma unroll
    for (int r = 0; r < 8; ++r) {
        const int base = (row0 + 2 * r) * IMG_W + col0;
        const float4 R = *(const float4*)(rp + base);
        const float4 G = *(const float4*)(gp + base);
        const float4 B = *(const float4*)(bp + base);
#pragma unroll
        for (int k = 0; k < 4; ++k) {
            const float Y = 0.212671f * (&R.x)[k] + 0.715160f * (&G.x)[k] +
                            0.072169f * (&B.x)[k];
            const float L = 116.0f * f_lab(Y) - 16.0f;
            int l8 = (int)rintf(L * 2.55f);
            l8 = min(max(l8, 0), 255);
            atomicAdd(&h[l8], 1u);
        }
    }
    __syncthreads();

    const int ty = blockIdx.y >> 4;              // tile row
    for (int i = tid; i < 2 * NBINS; i += 256) {
        const int t = i >> 8, bin = i & 255;
        const unsigned v = sh[t][0][bin] + sh[t][1][bin];
        if (v) atomicAdd(&g_hist[(ty * NT + blockIdx.x * 2 + t) * NBINS + bin], v);
    }
}

// ---------------------------------------------------------------------------
// Kernel 2: clip + redistribute + cdf -> LUT (exact fp32, matches reference).
// ---------------------------------------------------------------------------
__global__ __launch_bounds__(NBINS) void k_lut() {
    __shared__ float sv[NBINS];
    __shared__ unsigned int s_ex;
    const int t = threadIdx.x, b = blockIdx.x;
    if (t == 0) s_ex = 0u;
    __syncthreads();

    const unsigned h = g_hist[b * NBINS + t];
    const unsigned over = (h > 2560u) ? (h - 2560u) : 0u;  // clip = 10*65536/256
    if (over) atomicAdd(&s_ex, over);
    __syncthreads();

    sv[t] = (float)min(h, 2560u) + (float)s_ex * (1.0f / 256.0f);
    __syncthreads();
    if (t == 0) {
        float run = 0.0f;
#pragma unroll 8
        for (int i = 0; i < NBINS; ++i) { run += sv[i]; sv[i] = run; }
    }
    __syncthreads();

    float lut = rintf(sv[t] * (255.0f / 65536.0f));
    g_lut[b * NBINS + t] = fminf(fmaxf(lut, 0.0f), 255.0f);
}

// ---------------------------------------------------------------------------
// Kernel 3: apply. Block = 256 thr covers 16 rows x 512 cols, 4 px/thread
// via float4. Grid = (4, 128). The 512-col chunk touches x-tiles
// {2bx-1..2bx+2} (clamped); 16-row band has fixed (yt0, yt1). 4 x-slots of
// (y0,y1)-packed LUTs in shared => 2x LDS.64 per pixel.
// ---------------------------------------------------------------------------
__global__ __launch_bounds__(256) void k_apply(const float* __restrict__ in,
                                               float* __restrict__ out) {
    __shared__ float2 slut[4][NBINS];
    const int tid = threadIdx.x;
    const int bx = blockIdx.x, by = blockIdx.y;
    const int row_base = by * 16;

    const float fy0 = fminf(fmaxf((row_base + 0.5f) * (1.0f / 256.0f) - 0.5f, 0.0f), 7.0f);
    const int yt0 = (int)floorf(fy0);
    const int yt1 = min(yt0 + 1, NT - 1);

#pragma unroll
    for (int s = 0; s < 4; ++s) {
        const int xt = min(max(bx * 2 - 1 + s, 0), NT - 1);
        slut[s][tid] = make_float2(g_lut[(yt0 * NT + xt) * NBINS + tid],
                                   g_lut[(yt1 * NT + xt) * NBINS + tid]);
    }
    __syncthreads();

    const int col0 = bx * 512 + (tid & 127) * 4;
    const int row0 = row_base + (tid >> 7);

    // x-tile indices: constant across the 4-px group (boundaries at 128+256k,
    // which are 4-aligned)
    const float fxg = fminf(fmaxf((col0 + 0.5f) * (1.0f / 256.0f) - 0.5f, 0.0f), 7.0f);
    const int x0c = (int)floorf(fxg);
    const int xs0 = x0c - (bx * 2 - 1);               // slot in [0,3]
    const int xs1 = min(x0c + 1, NT - 1) - (bx * 2 - 1);

    float wxv[4];
#pragma unroll
    for (int k = 0; k < 4; ++k) {
        const float fx = fminf(fmaxf((col0 + k + 0.5f) * (1.0f / 256.0f) - 0.5f, 0.0f), 7.0f);
        wxv[k] = fx - (float)x0c;
    }

    const float* __restrict__ rp = in;
    const float* __restrict__ gp = in + NPIX;
    const float* __restrict__ bp = in + 2 * NPIX;

#pragma unroll 2
    for (int r = 0; r < 8; ++r) {
        const int row = row0 + 2 * r;
        const int idx = row * IMG_W + col0;
        const float4 R = *(const float4*)(rp + idx);
        const float4 G = *(const float4*)(gp + idx);
        const float4 B = *(const float4*)(bp + idx);

        const float fyr = fminf(fmaxf((row + 0.5f) * (1.0f / 256.0f) - 0.5f, 0.0f), 7.0f);
        const float wy = fyr - (float)yt0;

        float4 Ro, Go, Bo;
#pragma unroll
        for (int k = 0; k < 4; ++k) {
            const float rr = (&R.x)[k], gg = (&G.x)[k], bb = (&B.x)[k];

            const float Xv = (0.412453f * rr + 0.357580f * gg + 0.180423f * bb) *
                             (1.0f / 0.950456f);
            const float Yv = 0.212671f * rr + 0.715160f * gg + 0.072169f * bb;
            const float Zv = (0.019334f * rr + 0.119193f * gg + 0.950227f * bb) *
                             (1.0f / 1.088754f);
            const float fX = f_lab(Xv), fY = f_lab(Yv), fZ = f_lab(Zv);
            const float av = 500.0f * (fX - fY);
            const float bv = 200.0f * (fY - fZ);

            int l8 = (int)rintf((116.0f * fY - 16.0f) * 2.55f);
            l8 = min(max(l8, 0), 255);

            const float2 A = slut[xs0][l8];
            const float2 Bt = slut[xs1][l8];
            const float v0 = fmaf(wy, A.y - A.x, A.x);
            const float v1 = fmaf(wy, Bt.y - Bt.x, Bt.x);
            const float Leq = fmaf(wxv[k], v1 - v0, v0) * (100.0f / 255.0f);

            const float fy2 = (Leq + 16.0f) * (1.0f / 116.0f);
            const float fx2 = fy2 + av * (1.0f / 500.0f);
            const float fz2 = fy2 - bv * (1.0f / 200.0f);
            const float x3 = fx2 * fx2 * fx2;
            const float y3 = fy2 * fy2 * fy2;
            const float z3 = fz2 * fz2 * fz2;
            const float Xo = ((x3 > 0.008856f) ? x3
                              : (fx2 - 16.0f / 116.0f) * (1.0f / 7.787f)) * 0.950456f;
            const float Yo = ((y3 > 0.008856f) ? y3
                              : (fy2 - 16.0f / 116.0f) * (1.0f / 7.787f));
            const float Zo = ((z3 > 0.008856f) ? z3
                              : (fz2 - 16.0f / 116.0f) * (1.0f / 7.787f)) * 1.088754f;

            (&Ro.x)[k] = clamp01( 3.240479f * Xo - 1.537150f * Yo - 0.498535f * Zo);
            (&Go.x)[k] = clamp01(-0.969256f * Xo + 1.875992f * Yo + 0.041556f * Zo);
            (&Bo.x)[k] = clamp01( 0.055648f * Xo - 0.204043f * Yo + 1.057311f * Zo);
        }
        *(float4*)(out + idx)            = Ro;
        *(float4*)(out + NPIX + idx)     = Go;
        *(float4*)(out + 2 * NPIX + idx) = Bo;
    }
}

// ---------------------------------------------------------------------------
extern "C" void kernel_launch(void* const* d_in, const int* in_sizes, int n_in,
                              void* d_out, int out_size) {
    const float* in = (const float*)d_in[0];
    float* out = (float*)d_out;
    (void)in_sizes; (void)n_in; (void)out_size;

    k_zero<<<NT * NT, NBINS>>>();
    k_hist<<<dim3(4, 128), 256>>>(in, in + NPIX, in + 2 * NPIX);
    k_lut<<<NT * NT, NBINS>>>();
    k_apply<<<dim3(4, 128), 256>>>(in, out);
}

// round 6
// speedup vs baseline: 1.5104x; 1.0009x over previous
#include <cuda_runtime.h>
#include <stdint.h>

#define IMG_H 2048
#define IMG_W 2048
#define NPIX (IMG_H * IMG_W)
#define NT 8
#define NBINS 256

__device__ unsigned int g_hist[NT * NT * NBINS];
__device__ float g_lut[NT * NT * NBINS];

// fast cbrt for v in (0, ~1.1]: ex2(lg2(v)/3) via MUFU. ~1e-6 rel, 3 instrs.
__device__ __forceinline__ float cbrt_fast(float v) {
    float l, r;
    asm("lg2.approx.f32 %0, %1;" : "=f"(l) : "f"(v));
    l *= (1.0f / 3.0f);
    asm("ex2.approx.f32 %0, %1;" : "=f"(r) : "f"(l));
    return r;
}

__device__ __forceinline__ float f_lab(float v) {
    return (v > 0.008856f) ? cbrt_fast(v) : (7.787f * v + 16.0f / 116.0f);
}

__device__ __forceinline__ float clamp01(float v) {
    return fminf(fmaxf(v, 0.0f), 1.0f);
}

// ---------------------------------------------------------------------------
// Kernel 0: zero global hist (graph replays need deterministic state)
// ---------------------------------------------------------------------------
__global__ void k_zero() {
    g_hist[blockIdx.x * blockDim.x + threadIdx.x] = 0u;
}

// ---------------------------------------------------------------------------
// Kernel 1: per-tile histograms. Block = 256 thr covers 8 rows x 512 cols
// (2 x-tiles). Grid = (256 y-bands, 4 x-chunks) = 1024 blocks. Shared hist:
// 2 tiles x 2 replicas x 256 bins (replica = warp&1) halves ATOMS conflicts.
// ---------------------------------------------------------------------------
__global__ __launch_bounds__(256) void k_hist(const float* __restrict__ rp,
                                              const float* __restrict__ gp,
                                              const float* __restrict__ bp) {
    __shared__ unsigned int sh[2][2][NBINS];     // [tile][replica][bin]
    const int tid = threadIdx.x;
    for (int i = tid; i < 2 * 2 * NBINS; i += 256) ((unsigned*)sh)[i] = 0u;
    __syncthreads();

    const int col0 = blockIdx.y * 512 + (tid & 127) * 4;   // blockIdx.y in 0..3
    const int row0 = blockIdx.x * 8 + (tid >> 7);          // blockIdx.x in 0..255
    const int tl = (tid & 127) >> 6;             // local x-tile 0/1
    const int rep = (tid >> 5) & 1;
    unsigned int* __restrict__ h = sh[tl][rep];

#pragma unroll
    for (int r = 0; r < 4; ++r) {
        const int base = (row0 + 2 * r) * IMG_W + col0;
        const float4 R = *(const float4*)(rp + base);
        const float4 G = *(const float4*)(gp + base);
        const float4 B = *(const float4*)(bp + base);
#pragma unroll
        for (int k = 0; k < 4; ++k) {
            const float Y = 0.212671f * (&R.x)[k] + 0.715160f * (&G.x)[k] +
                            0.072169f * (&B.x)[k];
            const float L = 116.0f * f_lab(Y) - 16.0f;
            int l8 = (int)rintf(L * 2.55f);
            l8 = min(max(l8, 0), 255);
            atomicAdd(&h[l8], 1u);
        }
    }
    __syncthreads();

    const int ty = blockIdx.x >> 5;              // tile row (8-row bands, 32/tile)
    for (int i = tid; i < 2 * NBINS; i += 256) {
        const int t = i >> 8, bin = i & 255;
        const unsigned v = sh[t][0][bin] + sh[t][1][bin];
        if (v) atomicAdd(&g_hist[(ty * NT + blockIdx.y * 2 + t) * NBINS + bin], v);
    }
}

// ---------------------------------------------------------------------------
// Kernel 2: clip + redistribute + cdf -> LUT (exact fp32, matches reference).
// ---------------------------------------------------------------------------
__global__ __launch_bounds__(NBINS) void k_lut() {
    __shared__ float sv[NBINS];
    __shared__ unsigned int s_ex;
    const int t = threadIdx.x, b = blockIdx.x;
    if (t == 0) s_ex = 0u;
    __syncthreads();

    const unsigned h = g_hist[b * NBINS + t];
    const unsigned over = (h > 2560u) ? (h - 2560u) : 0u;  // clip = 10*65536/256
    if (over) atomicAdd(&s_ex, over);
    __syncthreads();

    sv[t] = (float)min(h, 2560u) + (float)s_ex * (1.0f / 256.0f);
    __syncthreads();
    if (t == 0) {
        float run = 0.0f;
#pragma unroll 8
        for (int i = 0; i < NBINS; ++i) { run += sv[i]; sv[i] = run; }
    }
    __syncthreads();

    float lut = rintf(sv[t] * (255.0f / 65536.0f));
    g_lut[b * NBINS + t] = fminf(fmaxf(lut, 0.0f), 255.0f);
}

// ---------------------------------------------------------------------------
// Kernel 3: apply. Block = 256 thr covers 8 rows x 512 cols, 4 px/thread
// via float4. Grid = (256 y-bands, 4 x-chunks) = 1024 blocks. The 512-col
// chunk touches x-tiles {2bx-1..2bx+2} (clamped); 8-row band has fixed
// (yt0, yt1) (y-boundaries at 128+256k are 8-aligned). 4 x-slots of
// (y0,y1)-packed LUTs in shared => 2x LDS.64 per pixel.
// ---------------------------------------------------------------------------
__global__ __launch_bounds__(256) void k_apply(const float* __restrict__ in,
                                               float* __restrict__ out) {
    __shared__ float2 slut[4][NBINS];
    const int tid = threadIdx.x;
    const int bx = blockIdx.y;       // x-chunk 0..3
    const int by = blockIdx.x;       // y-band 0..255
    const int row_base = by * 8;

    const float fy0 = fminf(fmaxf((row_base + 0.5f) * (1.0f / 256.0f) - 0.5f, 0.0f), 7.0f);
    const int yt0 = (int)floorf(fy0);
    const int yt1 = min(yt0 + 1, NT - 1);

#pragma unroll
    for (int s = 0; s < 4; ++s) {
        const int xt = min(max(bx * 2 - 1 + s, 0), NT - 1);
        slut[s][tid] = make_float2(g_lut[(yt0 * NT + xt) * NBINS + tid],
                                   g_lut[(yt1 * NT + xt) * NBINS + tid]);
    }
    __syncthreads();

    const int col0 = bx * 512 + (tid & 127) * 4;
    const int row0 = row_base + (tid >> 7);

    // x-tile slot: constant across the 4-px group (boundaries at 128+256k,
    // 4-aligned)
    const float fxg = fminf(fmaxf((col0 + 0.5f) * (1.0f / 256.0f) - 0.5f, 0.0f), 7.0f);
    const int x0c = (int)floorf(fxg);
    const int xs0 = x0c - (bx * 2 - 1);               // slot in [0,3]
    const int xs1 = min(x0c + 1, NT - 1) - (bx * 2 - 1);

    float wxv[4];
#pragma unroll
    for (int k = 0; k < 4; ++k) {
        const float fx = fminf(fmaxf((col0 + k + 0.5f) * (1.0f / 256.0f) - 0.5f, 0.0f), 7.0f);
        wxv[k] = fx - (float)x0c;
    }

    const float* __restrict__ rp = in;
    const float* __restrict__ gp = in + NPIX;
    const float* __restrict__ bp = in + 2 * NPIX;

#pragma unroll
    for (int r = 0; r < 4; ++r) {
        const int row = row0 + 2 * r;
        const int idx = row * IMG_W + col0;
        const float4 R = *(const float4*)(rp + idx);
        const float4 G = *(const float4*)(gp + idx);
        const float4 B = *(const float4*)(bp + idx);

        const float fyr = fminf(fmaxf((row + 0.5f) * (1.0f / 256.0f) - 0.5f, 0.0f), 7.0f);
        const float wy = fyr - (float)yt0;

        float4 Ro, Go, Bo;
#pragma unroll
        for (int k = 0; k < 4; ++k) {
            const float rr = (&R.x)[k], gg = (&G.x)[k], bb = (&B.x)[k];

            const float Xv = (0.412453f * rr + 0.357580f * gg + 0.180423f * bb) *
                             (1.0f / 0.950456f);
            const float Yv = 0.212671f * rr + 0.715160f * gg + 0.072169f * bb;
            const float Zv = (0.019334f * rr + 0.119193f * gg + 0.950227f * bb) *
                             (1.0f / 1.088754f);
            const float fX = f_lab(Xv), fY = f_lab(Yv), fZ = f_lab(Zv);
            const float av = 500.0f * (fX - fY);
            const float bv = 200.0f * (fY - fZ);

            int l8 = (int)rintf((116.0f * fY - 16.0f) * 2.55f);
            l8 = min(max(l8, 0), 255);

            const float2 A = slut[xs0][l8];
            const float2 Bt = slut[xs1][l8];
            const float v0 = fmaf(wy, A.y - A.x, A.x);
            const float v1 = fmaf(wy, Bt.y - Bt.x, Bt.x);
            const float Leq = fmaf(wxv[k], v1 - v0, v0) * (100.0f / 255.0f);

            const float fy2 = (Leq + 16.0f) * (1.0f / 116.0f);
            const float fx2 = fy2 + av * (1.0f / 500.0f);
            const float fz2 = fy2 - bv * (1.0f / 200.0f);
            const float x3 = fx2 * fx2 * fx2;
            const float y3 = fy2 * fy2 * fy2;
            const float z3 = fz2 * fz2 * fz2;
            const float Xo = ((x3 > 0.008856f) ? x3
                              : (fx2 - 16.0f / 116.0f) * (1.0f / 7.787f)) * 0.950456f;
            const float Yo = ((y3 > 0.008856f) ? y3
                              : (fy2 - 16.0f / 116.0f) * (1.0f / 7.787f));
            const float Zo = ((z3 > 0.008856f) ? z3
                              : (fz2 - 16.0f / 116.0f) * (1.0f / 7.787f)) * 1.088754f;

            (&Ro.x)[k] = clamp01( 3.240479f * Xo - 1.537150f * Yo - 0.498535f * Zo);
            (&Go.x)[k] = clamp01(-0.969256f * Xo + 1.875992f * Yo + 0.041556f * Zo);
            (&Bo.x)[k] = clamp01( 0.055648f * Xo - 0.204043f * Yo + 1.057311f * Zo);
        }
        *(float4*)(out + idx)            = Ro;
        *(float4*)(out + NPIX + idx)     = Go;
        *(float4*)(out + 2 * NPIX + idx) = Bo;
    }
}

// ---------------------------------------------------------------------------
extern "C" void kernel_launch(void* const* d_in, const int* in_sizes, int n_in,
                              void* d_out, int out_size) {
    const float* in = (const float*)d_in[0];
    float* out = (float*)d_out;
    (void)in_sizes; (void)n_in; (void)out_size;

    k_zero<<<NT * NT, NBINS>>>();
    k_hist<<<dim3(256, 4), 256>>>(in, in + NPIX, in + 2 * NPIX);
    k_lut<<<NT * NT, NBINS>>>();
    k_apply<<<dim3(256, 4), 256>>>(in, out);
}

// round 7
// speedup vs baseline: 1.5897x; 1.0525x over previous
#include <cuda_runtime.h>
#include <stdint.h>

#define IMG_H 2048
#define IMG_W 2048
#define NPIX (IMG_H * IMG_W)
#define NT 8
#define NBINS 256

__device__ unsigned int g_hist[NT * NT * NBINS];
__device__ float g_lut[NT * NT * NBINS];

// fast cbrt for v in (0, ~1.1]: ex2(lg2(v)/3) via MUFU. ~1e-6 rel, 3 instrs.
__device__ __forceinline__ float cbrt_fast(float v) {
    float l, r;
    asm("lg2.approx.f32 %0, %1;" : "=f"(l) : "f"(v));
    l *= (1.0f / 3.0f);
    asm("ex2.approx.f32 %0, %1;" : "=f"(r) : "f"(l));
    return r;
}

__device__ __forceinline__ float f_lab(float v) {
    return (v > 0.008856f) ? cbrt_fast(v) : (7.787f * v + 16.0f / 116.0f);
}

// ---------------------------------------------------------------------------
// Kernel 1: per-tile histograms. Block = 256 thr covers 8 rows x 512 cols
// (2 x-tiles). Grid = (256 y-bands, 4 x-chunks) = 1024 blocks. Shared hist:
// 2 tiles x 2 replicas x 256 bins (replica = warp&1) halves ATOMS conflicts.
// g_hist must be zero on entry (zero-init at load; k_lut re-zeroes it).
// ---------------------------------------------------------------------------
__global__ __launch_bounds__(256) void k_hist(const float* __restrict__ rp,
                                              const float* __restrict__ gp,
                                              const float* __restrict__ bp) {
    __shared__ unsigned int sh[2][2][NBINS];     // [tile][replica][bin]
    const int tid = threadIdx.x;
    for (int i = tid; i < 2 * 2 * NBINS; i += 256) ((unsigned*)sh)[i] = 0u;
    __syncthreads();

    const int col0 = blockIdx.y * 512 + (tid & 127) * 4;   // blockIdx.y in 0..3
    const int row0 = blockIdx.x * 8 + (tid >> 7);          // blockIdx.x in 0..255
    const int tl = (tid & 127) >> 6;             // local x-tile 0/1
    const int rep = (tid >> 5) & 1;
    unsigned int* __restrict__ h = sh[tl][rep];

#pragma unroll
    for (int r = 0; r < 4; ++r) {
        const int base = (row0 + 2 * r) * IMG_W + col0;
        const float4 R = *(const float4*)(rp + base);
        const float4 G = *(const float4*)(gp + base);
        const float4 B = *(const float4*)(bp + base);
#pragma unroll
        for (int k = 0; k < 4; ++k) {
            const float Y = 0.212671f * (&R.x)[k] + 0.715160f * (&G.x)[k] +
                            0.072169f * (&B.x)[k];
            const float L = 116.0f * f_lab(Y) - 16.0f;
            int l8 = (int)rintf(L * 2.55f);
            l8 = min(max(l8, 0), 255);
            atomicAdd(&h[l8], 1u);
        }
    }
    __syncthreads();

    const int ty = blockIdx.x >> 5;              // tile row (8-row bands, 32/tile)
    for (int i = tid; i < 2 * NBINS; i += 256) {
        const int t = i >> 8, bin = i & 255;
        const unsigned v = sh[t][0][bin] + sh[t][1][bin];
        if (v) atomicAdd(&g_hist[(ty * NT + blockIdx.y * 2 + t) * NBINS + bin], v);
    }
}

// ---------------------------------------------------------------------------
// Kernel 2: clip + redistribute + cdf -> LUT (exact fp32, matches reference).
// Also resets g_hist to zero for the next graph replay (replaces k_zero).
// ---------------------------------------------------------------------------
__global__ __launch_bounds__(NBINS) void k_lut() {
    __shared__ float sv[NBINS];
    __shared__ unsigned int s_ex;
    const int t = threadIdx.x, b = blockIdx.x;
    if (t == 0) s_ex = 0u;
    __syncthreads();

    const unsigned h = g_hist[b * NBINS + t];
    g_hist[b * NBINS + t] = 0u;                  // reset for next replay
    const unsigned over = (h > 2560u) ? (h - 2560u) : 0u;  // clip = 10*65536/256
    if (over) atomicAdd(&s_ex, over);
    __syncthreads();

    sv[t] = (float)min(h, 2560u) + (float)s_ex * (1.0f / 256.0f);
    __syncthreads();
    if (t == 0) {
        float run = 0.0f;
#pragma unroll 8
        for (int i = 0; i < NBINS; ++i) { run += sv[i]; sv[i] = run; }
    }
    __syncthreads();

    float lut = rintf(sv[t] * (255.0f / 65536.0f));
    g_lut[b * NBINS + t] = fminf(fmaxf(lut, 0.0f), 255.0f);
}

// ---------------------------------------------------------------------------
// Kernel 3: apply. Block = 256 thr covers 8 rows x 512 cols, 4 px/thread.
// Grid = (256 y-bands, 4 x-chunks). Algebraic folds:
//   a/500 == fX-fY, b/200 == fY-fZ  (the x500 / /500 round-trip cancels)
//   => fx2 = fX + d, fz2 = fZ + d where d = fy2 - fY.
//   White point folded into the output matrix columns; 100/255 & /116 folded
//   into one FMA; linear path folded; .SAT via __saturatef.
// ---------------------------------------------------------------------------
__global__ __launch_bounds__(256, 6) void k_apply(const float* __restrict__ in,
                                                  float* __restrict__ out) {
    __shared__ float2 slut[4][NBINS];
    const int tid = threadIdx.x;
    const int bx = blockIdx.y;       // x-chunk 0..3
    const int by = blockIdx.x;       // y-band 0..255
    const int row_base = by * 8;

    const float fy0 = fminf(fmaxf((row_base + 0.5f) * (1.0f / 256.0f) - 0.5f, 0.0f), 7.0f);
    const int yt0 = (int)floorf(fy0);
    const int yt1 = min(yt0 + 1, NT - 1);

#pragma unroll
    for (int s = 0; s < 4; ++s) {
        const int xt = min(max(bx * 2 - 1 + s, 0), NT - 1);
        slut[s][tid] = make_float2(g_lut[(yt0 * NT + xt) * NBINS + tid],
                                   g_lut[(yt1 * NT + xt) * NBINS + tid]);
    }
    __syncthreads();

    const int col0 = bx * 512 + (tid & 127) * 4;
    const int row0 = row_base + (tid >> 7);

    const float fxg = fminf(fmaxf((col0 + 0.5f) * (1.0f / 256.0f) - 0.5f, 0.0f), 7.0f);
    const int x0c = (int)floorf(fxg);
    const int xs0 = x0c - (bx * 2 - 1);               // slot in [0,3]
    const int xs1 = min(x0c + 1, NT - 1) - (bx * 2 - 1);

    float wxv[4];
#pragma unroll
    for (int k = 0; k < 4; ++k) {
        const float fx = fminf(fmaxf((col0 + k + 0.5f) * (1.0f / 256.0f) - 0.5f, 0.0f), 7.0f);
        wxv[k] = fx - (float)x0c;
    }

    const float* __restrict__ rp = in;
    const float* __restrict__ gp = in + NPIX;
    const float* __restrict__ bp = in + 2 * NPIX;

#pragma unroll
    for (int r = 0; r < 4; ++r) {
        const int row = row0 + 2 * r;
        const int idx = row * IMG_W + col0;
        const float4 R = *(const float4*)(rp + idx);
        const float4 G = *(const float4*)(gp + idx);
        const float4 B = *(const float4*)(bp + idx);

        const float fyr = fminf(fmaxf((row + 0.5f) * (1.0f / 256.0f) - 0.5f, 0.0f), 7.0f);
        const float wy = fyr - (float)yt0;

        float4 Ro, Go, Bo;
#pragma unroll
        for (int k = 0; k < 4; ++k) {
            const float rr = (&R.x)[k], gg = (&G.x)[k], bb = (&B.x)[k];

            const float Xv = (0.412453f * rr + 0.357580f * gg + 0.180423f * bb) *
                             (1.0f / 0.950456f);
            const float Yv = 0.212671f * rr + 0.715160f * gg + 0.072169f * bb;
            const float Zv = (0.019334f * rr + 0.119193f * gg + 0.950227f * bb) *
                             (1.0f / 1.088754f);
            const float fX = f_lab(Xv), fY = f_lab(Yv), fZ = f_lab(Zv);

            int l8 = (int)rintf(fmaf(fY, 295.8f, -40.8f));   // (116 fY - 16)*2.55
            l8 = min(max(l8, 0), 255);

            const float2 A = slut[xs0][l8];
            const float2 Bt = slut[xs1][l8];
            const float v0 = fmaf(wy, A.y - A.x, A.x);
            const float v1 = fmaf(wy, Bt.y - Bt.x, Bt.x);
            const float lutv = fmaf(wxv[k], v1 - v0, v0);

            // fy2 = (lutv*100/255 + 16)/116 ; d = fy2 - fY
            const float fy2 = fmaf(lutv, 100.0f / (255.0f * 116.0f), 16.0f / 116.0f);
            const float d = fy2 - fY;
            const float fx2 = fX + d;
            const float fz2 = fZ + d;

            const float x3 = fx2 * fx2 * fx2;
            const float y3 = fy2 * fy2 * fy2;
            const float z3 = fz2 * fz2 * fz2;
            // linear path: (f - 16/116)/7.787 = f*0.1284191 - 0.0177129
            const float Xo = (x3 > 0.008856f) ? x3
                             : fmaf(fx2, 0.1284191f, -0.0177129f);
            const float Yo = (y3 > 0.008856f) ? y3
                             : fmaf(fy2, 0.1284191f, -0.0177129f);
            const float Zo = (z3 > 0.008856f) ? z3
                             : fmaf(fz2, 0.1284191f, -0.0177129f);

            // output matrix with white point folded into columns 0 and 2
            (&Ro.x)[k] = __saturatef( 3.0799327f * Xo - 1.537150f * Yo - 0.5427823f * Zo);
            (&Go.x)[k] = __saturatef(-0.9212352f * Xo + 1.875992f * Yo + 0.0452442f * Zo);
            (&Bo.x)[k] = __saturatef( 0.0528910f * Xo - 0.204043f * Yo + 1.1511516f * Zo);
        }
        *(float4*)(out + idx)            = Ro;
        *(float4*)(out + NPIX + idx)     = Go;
        *(float4*)(out + 2 * NPIX + idx) = Bo;
    }
}

// ---------------------------------------------------------------------------
extern "C" void kernel_launch(void* const* d_in, const int* in_sizes, int n_in,
                              void* d_out, int out_size) {
    const float* in = (const float*)d_in[0];
    float* out = (float*)d_out;
    (void)in_sizes; (void)n_in; (void)out_size;

    k_hist<<<dim3(256, 4), 256>>>(in, in + NPIX, in + 2 * NPIX);
    k_lut<<<NT * NT, NBINS>>>();
    k_apply<<<dim3(256, 4), 256>>>(in, out);
}

// round 8
// speedup vs baseline: 1.6019x; 1.0077x over previous
#include <cuda_runtime.h>
#include <stdint.h>

#define IMG_H 2048
#define IMG_W 2048
#define NPIX (IMG_H * IMG_W)
#define NT 8
#define NBINS 256

__device__ unsigned int g_hist[NT * NT * NBINS];
__device__ float g_lut[NT * NT * NBINS];

// fast cbrt for v in (0, ~1.1]: ex2(lg2(v)/3) via MUFU. ~1e-6 rel, 3 instrs.
__device__ __forceinline__ float cbrt_fast(float v) {
    float l, r;
    asm("lg2.approx.f32 %0, %1;" : "=f"(l) : "f"(v));
    l *= (1.0f / 3.0f);
    asm("ex2.approx.f32 %0, %1;" : "=f"(r) : "f"(l));
    return r;
}

__device__ __forceinline__ float f_lab(float v) {
    return (v > 0.008856f) ? cbrt_fast(v) : (7.787f * v + 16.0f / 116.0f);
}

// ---------------------------------------------------------------------------
// Kernel 1: per-tile histograms. Block = 256 thr covers 8 rows x 512 cols
// (2 x-tiles). Grid = (256 y-bands, 4 x-chunks) = 1024 blocks.
// All 12 float4 loads are batched up front (MLP=12) to hide DRAM latency.
// Shared hist: 2 tiles x 4 replicas (one PER WARP) -> no cross-warp ATOMS
// serialization. g_hist must be zero on entry (load-time zero-init; k_lut
// re-zeroes it each run).
// ---------------------------------------------------------------------------
__global__ __launch_bounds__(256) void k_hist(const float* __restrict__ rp,
                                              const float* __restrict__ gp,
                                              const float* __restrict__ bp) {
    __shared__ unsigned int sh[2][4][NBINS];     // [tile][replica][bin] 8KB
    const int tid = threadIdx.x;
    for (int i = tid; i < 2 * 4 * NBINS; i += 256) ((unsigned*)sh)[i] = 0u;
    __syncthreads();

    const int col0 = blockIdx.y * 512 + (tid & 127) * 4;   // blockIdx.y in 0..3
    const int row0 = blockIdx.x * 8 + (tid >> 7);          // blockIdx.x in 0..255
    const int wid = tid >> 5;                    // 0..7
    const int tl = (wid >> 1) & 1;               // == (tid&127)>>6 : x-tile 0/1
    const int rep = (wid & 1) | ((wid >> 2) << 1);   // unique replica per warp
    unsigned int* __restrict__ h = sh[tl][rep];

    // batch ALL loads first: 12 independent float4 -> deep MLP
    float4 Rv[4], Gv[4], Bv[4];
#pragma unroll
    for (int r = 0; r < 4; ++r) {
        const int base = (row0 + 2 * r) * IMG_W + col0;
        Rv[r] = *(const float4*)(rp + base);
        Gv[r] = *(const float4*)(gp + base);
        Bv[r] = *(const float4*)(bp + base);
    }

#pragma unroll
    for (int r = 0; r < 4; ++r) {
#pragma unroll
        for (int k = 0; k < 4; ++k) {
            const float Y = 0.212671f * (&Rv[r].x)[k] + 0.715160f * (&Gv[r].x)[k] +
                            0.072169f * (&Bv[r].x)[k];
            const float L = 116.0f * f_lab(Y) - 16.0f;
            int l8 = (int)rintf(L * 2.55f);
            l8 = min(max(l8, 0), 255);
            atomicAdd(&h[l8], 1u);
        }
    }
    __syncthreads();

    const int ty = blockIdx.x >> 5;              // tile row (8-row bands, 32/tile)
    for (int i = tid; i < 2 * NBINS; i += 256) {
        const int t = i >> 8, bin = i & 255;
        const unsigned v = sh[t][0][bin] + sh[t][1][bin] +
                           sh[t][2][bin] + sh[t][3][bin];
        if (v) atomicAdd(&g_hist[(ty * NT + blockIdx.y * 2 + t) * NBINS + bin], v);
    }
}

// ---------------------------------------------------------------------------
// Kernel 2: clip + redistribute + cdf -> LUT (exact fp32, matches reference).
// Also resets g_hist to zero for the next graph replay.
// ---------------------------------------------------------------------------
__global__ __launch_bounds__(NBINS) void k_lut() {
    __shared__ float sv[NBINS];
    __shared__ unsigned int s_ex;
    const int t = threadIdx.x, b = blockIdx.x;
    if (t == 0) s_ex = 0u;
    __syncthreads();

    const unsigned h = g_hist[b * NBINS + t];
    g_hist[b * NBINS + t] = 0u;                  // reset for next replay
    const unsigned over = (h > 2560u) ? (h - 2560u) : 0u;  // clip = 10*65536/256
    if (over) atomicAdd(&s_ex, over);
    __syncthreads();

    sv[t] = (float)min(h, 2560u) + (float)s_ex * (1.0f / 256.0f);
    __syncthreads();
    if (t == 0) {
        float run = 0.0f;
#pragma unroll 8
        for (int i = 0; i < NBINS; ++i) { run += sv[i]; sv[i] = run; }
    }
    __syncthreads();

    float lut = rintf(sv[t] * (255.0f / 65536.0f));
    g_lut[b * NBINS + t] = fminf(fmaxf(lut, 0.0f), 255.0f);
}

// ---------------------------------------------------------------------------
// Kernel 3: apply. Block = 256 thr covers 8 rows x 512 cols, 4 px/thread.
// Grid = (256 y-bands, 4 x-chunks). Algebraic folds:
//   a/500 == fX-fY, b/200 == fY-fZ  => fx2 = fX + d, fz2 = fZ + d,
//   d = fy2 - fY; white point folded into output matrix; .SAT saturate.
// ---------------------------------------------------------------------------
__global__ __launch_bounds__(256, 6) void k_apply(const float* __restrict__ in,
                                                  float* __restrict__ out) {
    __shared__ float2 slut[4][NBINS];
    const int tid = threadIdx.x;
    const int bx = blockIdx.y;       // x-chunk 0..3
    const int by = blockIdx.x;       // y-band 0..255
    const int row_base = by * 8;

    const float fy0 = fminf(fmaxf((row_base + 0.5f) * (1.0f / 256.0f) - 0.5f, 0.0f), 7.0f);
    const int yt0 = (int)floorf(fy0);
    const int yt1 = min(yt0 + 1, NT - 1);

#pragma unroll
    for (int s = 0; s < 4; ++s) {
        const int xt = min(max(bx * 2 - 1 + s, 0), NT - 1);
        slut[s][tid] = make_float2(g_lut[(yt0 * NT + xt) * NBINS + tid],
                                   g_lut[(yt1 * NT + xt) * NBINS + tid]);
    }
    __syncthreads();

    const int col0 = bx * 512 + (tid & 127) * 4;
    const int row0 = row_base + (tid >> 7);

    const float fxg = fminf(fmaxf((col0 + 0.5f) * (1.0f / 256.0f) - 0.5f, 0.0f), 7.0f);
    const int x0c = (int)floorf(fxg);
    const int xs0 = x0c - (bx * 2 - 1);               // slot in [0,3]
    const int xs1 = min(x0c + 1, NT - 1) - (bx * 2 - 1);

    float wxv[4];
#pragma unroll
    for (int k = 0; k < 4; ++k) {
        const float fx = fminf(fmaxf((col0 + k + 0.5f) * (1.0f / 256.0f) - 0.5f, 0.0f), 7.0f);
        wxv[k] = fx - (float)x0c;
    }

    const float* __restrict__ rp = in;
    const float* __restrict__ gp = in + NPIX;
    const float* __restrict__ bp = in + 2 * NPIX;

#pragma unroll
    for (int r = 0; r < 4; ++r) {
        const int row = row0 + 2 * r;
        const int idx = row * IMG_W + col0;
        const float4 R = *(const float4*)(rp + idx);
        const float4 G = *(const float4*)(gp + idx);
        const float4 B = *(const float4*)(bp + idx);

        const float fyr = fminf(fmaxf((row + 0.5f) * (1.0f / 256.0f) - 0.5f, 0.0f), 7.0f);
        const float wy = fyr - (float)yt0;

        float4 Ro, Go, Bo;
#pragma unroll
        for (int k = 0; k < 4; ++k) {
            const float rr = (&R.x)[k], gg = (&G.x)[k], bb = (&B.x)[k];

            const float Xv = (0.412453f * rr + 0.357580f * gg + 0.180423f * bb) *
                             (1.0f / 0.950456f);
            const float Yv = 0.212671f * rr + 0.715160f * gg + 0.072169f * bb;
            const float Zv = (0.019334f * rr + 0.119193f * gg + 0.950227f * bb) *
                             (1.0f / 1.088754f);
            const float fX = f_lab(Xv), fY = f_lab(Yv), fZ = f_lab(Zv);

            int l8 = (int)rintf(fmaf(fY, 295.8f, -40.8f));   // (116 fY - 16)*2.55
            l8 = min(max(l8, 0), 255);

            const float2 A = slut[xs0][l8];
            const float2 Bt = slut[xs1][l8];
            const float v0 = fmaf(wy, A.y - A.x, A.x);
            const float v1 = fmaf(wy, Bt.y - Bt.x, Bt.x);
            const float lutv = fmaf(wxv[k], v1 - v0, v0);

            const float fy2 = fmaf(lutv, 100.0f / (255.0f * 116.0f), 16.0f / 116.0f);
            const float d = fy2 - fY;
            const float fx2 = fX + d;
            const float fz2 = fZ + d;

            const float x3 = fx2 * fx2 * fx2;
            const float y3 = fy2 * fy2 * fy2;
            const float z3 = fz2 * fz2 * fz2;
            const float Xo = (x3 > 0.008856f) ? x3
                             : fmaf(fx2, 0.1284191f, -0.0177129f);
            const float Yo = (y3 > 0.008856f) ? y3
                             : fmaf(fy2, 0.1284191f, -0.0177129f);
            const float Zo = (z3 > 0.008856f) ? z3
                             : fmaf(fz2, 0.1284191f, -0.0177129f);

            (&Ro.x)[k] = __saturatef( 3.0799327f * Xo - 1.537150f * Yo - 0.5427823f * Zo);
            (&Go.x)[k] = __saturatef(-0.9212352f * Xo + 1.875992f * Yo + 0.0452442f * Zo);
            (&Bo.x)[k] = __saturatef( 0.0528910f * Xo - 0.204043f * Yo + 1.1511516f * Zo);
        }
        *(float4*)(out + idx)            = Ro;
        *(float4*)(out + NPIX + idx)     = Go;
        *(float4*)(out + 2 * NPIX + idx) = Bo;
    }
}

// ---------------------------------------------------------------------------
extern "C" void kernel_launch(void* const* d_in, const int* in_sizes, int n_in,
                              void* d_out, int out_size) {
    const float* in = (const float*)d_in[0];
    float* out = (float*)d_out;
    (void)in_sizes; (void)n_in; (void)out_size;

    k_hist<<<dim3(256, 4), 256>>>(in, in + NPIX, in + 2 * NPIX);
    k_lut<<<NT * NT, NBINS>>>();
    k_apply<<<dim3(256, 4), 256>>>(in, out);
}